// round 14
// baseline (speedup 1.0000x reference)
#include <cuda_runtime.h>
#include <math.h>

// Problem constants (fixed by reference_code)
#define HP   2080            // padded height = H + 2*margin
#define WP   2080            // padded width
#define OW   2048            // output width
#define OH   2048            // output height
#define MARG 16
#define RAD  12              // truncation radius (measured rel_err 1.6e-4 << 1e-3)
#define KW   (2*RAD + 1)     // 25 taps
#define OFF  (MARG - RAD)    // 4; no circular wrap needed (OFF >= 0)

// Closed-form real-space taps (exact by Poisson summation; images ~e^-2e5):
//   h[t] = SIG*sqrt(2*pi) * exp(-2*pi^2*SIG^2 * t^2)
#define H_A  0.12533141373155003f   // 0.05 * sqrt(2*pi)
#define H_B  0.04934802200544679f   // 2*pi^2*0.05^2

// Fused-conv tiling: output tile 64 cols x 128 rows, one resident wave
#define TCW  64              // tile cols (output)
#define TRW  128             // tile rows (output)
#define HAL  (2*RAD)         // 24
#define INR  (TRW + HAL)     // 152 staged rows
#define INC  (TCW + HAL)     // 88 staged cols
#define SSTR 92              // smem row stride (floats): 16B aligned, conflict-friendly
#define PH   (INR / 2)       // 76 rows per h-pass phase
#define PITEMS (PH * 8)      // 608 items per phase
#define SMEM_CONV (INR * SSTR * 4)   // 55936 B dynamic

// Scratch (device global: alloc-free per harness rules)
__device__ float g_pad[HP * WP];   // padded splat canvas

// ---------------------------------------------------------------------------
// 1) Direct bilinear splat, min-word atomic mix:
//    cx even -> 2x red.v2 (2 trans, 4 words); cx odd -> 4x scalar red
//    (4 trans, 4 words; covers quad-span and the wrap cell cx=2079).
// ---------------------------------------------------------------------------
__device__ __forceinline__ void red2(float* p, float a, float b) {
    asm volatile("red.global.add.v2.f32 [%0], {%1, %2};"
                 :: "l"(p), "f"(a), "f"(b) : "memory");
}

__global__ void splat_kernel(const float2* __restrict__ pos,
                             const float*  __restrict__ inten, int n) {
    int i = blockIdx.x * blockDim.x + threadIdx.x;
    if (i >= n) return;
    float2 p = pos[i];
    float px = p.x + (float)MARG;
    float py = p.y + (float)MARG;
    int cx = (int)floorf(px);
    int cy = (int)floorf(py);
    cx = min(max(cx, 0), WP - 1);
    cy = min(max(cy, 0), HP - 1);
    float dx = px - (float)cx;
    float dy = py - (float)cy;
    int cy1 = cy + 1; if (cy1 >= HP) cy1 = 0;
    float I = inten[i];
    float w00 = (1.f - dy) * (1.f - dx) * I;
    float w01 = (1.f - dy) * dx * I;
    float w10 = dy * (1.f - dx) * I;
    float w11 = dy * dx * I;
    int ra = cy  * WP;
    int rb = cy1 * WP;
    if ((cx & 1) == 0) {                    // 8B-aligned pair (cx, cx+1); cx+1 <= 2079
        red2(&g_pad[ra + cx], w00, w01);
        red2(&g_pad[rb + cx], w10, w11);
    } else {                                // odd cx: 4 scalar words (wrap-safe)
        int cx1 = cx + 1; if (cx1 >= WP) cx1 = 0;
        atomicAdd(&g_pad[ra + cx ], w00);
        atomicAdd(&g_pad[rb + cx ], w10);
        atomicAdd(&g_pad[ra + cx1], w01);
        atomicAdd(&g_pad[rb + cx1], w11);
    }
}

// ---------------------------------------------------------------------------
// 2) Fused separable convolution + crop. One block = 64x128 output tile.
//    Taps computed inline (closed form). Stage 152x88 in dynamic smem;
//    two-phase in-place h-pass; v-pass 2 x (40-float reg window, 16 outputs).
//    512 blocks at 4/SM -> single resident wave.
// ---------------------------------------------------------------------------
extern __shared__ float s[];
__global__ void __launch_bounds__(256, 4) conv_kernel(float* __restrict__ out) {
    __shared__ float hh[KW];
    const int lt = threadIdx.x;
    const int c0 = blockIdx.x * TCW;
    const int r0 = blockIdx.y * TRW;
    if (lt < KW) {
        float t = (float)(lt - RAD);
        hh[lt] = H_A * expf(-H_B * t * t);
    }

    // Stage: canvas rows r0+OFF .. +151, cols c0+OFF .. +87 (22 float4/row)
    for (int idx = lt; idx < INR * (INC / 4); idx += 256) {
        int row = idx / (INC / 4);
        int c4  = idx % (INC / 4);
        *reinterpret_cast<float4*>(&s[row * SSTR + c4 * 4]) =
            *reinterpret_cast<const float4*>(&g_pad[(r0 + OFF + row) * WP + c0 + OFF + c4 * 4]);
    }
    __syncthreads();

    // h-pass, two row-disjoint phases with in-place writeback.
#pragma unroll
    for (int ph = 0; ph < 2; ph++) {
        float acc[3][8];
#pragma unroll
        for (int it = 0; it < 3; it++) {
            int w = lt + it * 256;
#pragma unroll
            for (int j = 0; j < 8; j++) acc[it][j] = 0.f;
            if (w < PITEMS) {
                int row = ph * PH + (w % PH);
                int g   = w / PH;
                float x[32];
#pragma unroll
                for (int m = 0; m < 8; m++) {
                    float4 v = *reinterpret_cast<float4*>(&s[row * SSTR + g * 8 + m * 4]);
                    x[4 * m + 0] = v.x; x[4 * m + 1] = v.y;
                    x[4 * m + 2] = v.z; x[4 * m + 3] = v.w;
                }
#pragma unroll
                for (int u = 0; u < KW; u++) {
                    float hv = hh[u];
#pragma unroll
                    for (int j = 0; j < 8; j++)
                        acc[it][j] = fmaf(hv, x[u + j], acc[it][j]);
                }
            }
        }
        __syncthreads();
#pragma unroll
        for (int it = 0; it < 3; it++) {
            int w = lt + it * 256;
            if (w < PITEMS) {
                int row = ph * PH + (w % PH);
                int g   = w / PH;
                *reinterpret_cast<float4*>(&s[row * SSTR + g * 8]) =
                    make_float4(acc[it][0], acc[it][1], acc[it][2], acc[it][3]);
                *reinterpret_cast<float4*>(&s[row * SSTR + g * 8 + 4]) =
                    make_float4(acc[it][4], acc[it][5], acc[it][6], acc[it][7]);
            }
        }
        __syncthreads();
    }

    // v-pass: thread -> col c0+tx; two 16-row groups rg = ty, ty+4
    const int tx = lt & 63;
    const int ty = lt >> 6;
#pragma unroll
    for (int q = 0; q < 2; q++) {
        const int rg = ty + 4 * q;          // 0..7
        float x[16 + HAL];                  // 40
#pragma unroll
        for (int k = 0; k < 16 + HAL; k++) x[k] = s[(rg * 16 + k) * SSTR + tx];
        float a[16];
#pragma unroll
        for (int i = 0; i < 16; i++) a[i] = 0.f;
#pragma unroll
        for (int u = 0; u < KW; u++) {
            float hv = hh[u];
#pragma unroll
            for (int i = 0; i < 16; i++)
                a[i] = fmaf(hv, x[u + i], a[i]);
        }
#pragma unroll
        for (int i = 0; i < 16; i++)
            out[(r0 + rg * 16 + i) * OW + c0 + tx] = a[i];
    }
}

// ---------------------------------------------------------------------------
extern "C" void kernel_launch(void* const* d_in, const int* in_sizes, int n_in,
                              void* d_out, int out_size) {
    const float2* pos   = (const float2*)d_in[0];   // (N,2) float32 (x, y)
    const float*  inten = (const float*) d_in[1];   // (N,) float32
    const int n = in_sizes[1];
    float* out = (float*)d_out;

    cudaFuncSetAttribute(conv_kernel, cudaFuncAttributeMaxDynamicSharedMemorySize, SMEM_CONV);

    // Zero the canvas via a graph memset node (driver path saturates L2 writes)
    void* pad_ptr = nullptr;
    cudaGetSymbolAddress(&pad_ptr, g_pad);
    cudaMemsetAsync(pad_ptr, 0, (size_t)HP * WP * sizeof(float), 0);

    splat_kernel<<<(n + 255) / 256, 256>>>(pos, inten, n);
    conv_kernel<<<dim3(OW / TCW, OH / TRW), 256, SMEM_CONV>>>(out);
}

// round 16
// speedup vs baseline: 1.0060x; 1.0060x over previous
#include <cuda_runtime.h>
#include <math.h>

// Problem constants (fixed by reference_code)
#define HP   2080            // padded height = H + 2*margin
#define WP   2080            // padded width
#define OW   2048            // output width
#define OH   2048            // output height
#define MARG 16
#define RAD  12              // truncation radius (measured rel_err 1.6e-4 << 1e-3)
#define KW   (2*RAD + 1)     // 25 taps
#define OFF  (MARG - RAD)    // 4; no circular wrap needed (OFF >= 0)

// Closed-form real-space taps (exact by Poisson summation; images ~e^-2e5):
//   h[t] = SIG*sqrt(2*pi) * exp(-2*pi^2*SIG^2 * t^2)
#define H_A  0.12533141373155003f   // 0.05 * sqrt(2*pi)
#define H_B  0.04934802200544679f   // 2*pi^2*0.05^2

// Fused-conv tiling: output tile 64 cols x 128 rows
#define TCW  64              // tile cols (output)
#define TRW  128             // tile rows (output)
#define HAL  (2*RAD)         // 24
#define INR  (TRW + HAL)     // 152 staged rows
#define INC  (TCW + HAL)     // 88 staged cols
#define SSTR 88              // smem row stride: 53504B/block -> 4 blocks/SM resident
#define PH   (INR / 2)       // 76 rows per h-pass phase
#define PITEMS (PH * 8)      // 608 items per phase
#define SMEM_CONV (INR * SSTR * 4)   // 53504 B dynamic

// Scratch (device global: alloc-free per harness rules)
__device__ float g_pad[HP * WP];   // padded splat canvas

// ---------------------------------------------------------------------------
// 1) Direct bilinear splat — transaction-minimal mix (R13-validated):
//    cx even      -> 2x red.v2 (2 trans)
//    cx % 4 == 1  -> 2x red.v4 (2 trans; cells at quad slots 1,2)
//    cx % 4 == 3  -> 4x scalar (4 trans; spans quads / wrap-safe)
//    avg 2.5 trans/point.
// ---------------------------------------------------------------------------
__device__ __forceinline__ void red4(float* p, float a, float b, float c, float d) {
    asm volatile("red.global.add.v4.f32 [%0], {%1, %2, %3, %4};"
                 :: "l"(p), "f"(a), "f"(b), "f"(c), "f"(d) : "memory");
}
__device__ __forceinline__ void red2(float* p, float a, float b) {
    asm volatile("red.global.add.v2.f32 [%0], {%1, %2};"
                 :: "l"(p), "f"(a), "f"(b) : "memory");
}

__global__ void splat_kernel(const float2* __restrict__ pos,
                             const float*  __restrict__ inten, int n) {
    int i = blockIdx.x * blockDim.x + threadIdx.x;
    if (i >= n) return;
    float2 p = pos[i];
    float px = p.x + (float)MARG;
    float py = p.y + (float)MARG;
    int cx = (int)floorf(px);
    int cy = (int)floorf(py);
    cx = min(max(cx, 0), WP - 1);
    cy = min(max(cy, 0), HP - 1);
    float dx = px - (float)cx;
    float dy = py - (float)cy;
    int cy1 = cy + 1; if (cy1 >= HP) cy1 = 0;
    float I = inten[i];
    float w00 = (1.f - dy) * (1.f - dx) * I;
    float w01 = (1.f - dy) * dx * I;
    float w10 = dy * (1.f - dx) * I;
    float w11 = dy * dx * I;
    int ra = cy  * WP;
    int rb = cy1 * WP;
    int m4 = cx & 3;
    if ((cx & 1) == 0) {                    // 8B-aligned pair (cx, cx+1); cx+1 <= 2079
        red2(&g_pad[ra + cx], w00, w01);
        red2(&g_pad[rb + cx], w10, w11);
    } else if (m4 == 1) {                   // cells at quad slots 1,2
        int b = cx & ~3;
        red4(&g_pad[ra + b], 0.f, w00, w01, 0.f);
        red4(&g_pad[rb + b], 0.f, w10, w11, 0.f);
    } else {                                // m4 == 3: spans quads (incl. wrap cx=2079)
        int cx1 = cx + 1; if (cx1 >= WP) cx1 = 0;
        atomicAdd(&g_pad[ra + cx ], w00);
        atomicAdd(&g_pad[rb + cx ], w10);
        atomicAdd(&g_pad[ra + cx1], w01);
        atomicAdd(&g_pad[rb + cx1], w11);
    }
}

// ---------------------------------------------------------------------------
// 2) Fused separable convolution + crop. One block = 64x128 output tile.
//    Taps inline (closed form). Stage 152x88 in dynamic smem (53.5KB ->
//    4 blocks/SM, 512-block single wave); two-phase in-place h-pass;
//    v-pass 2 x (40-float reg window, 16 outputs).
// ---------------------------------------------------------------------------
extern __shared__ float s[];
__global__ void __launch_bounds__(256, 4) conv_kernel(float* __restrict__ out) {
    __shared__ float hh[KW];
    const int lt = threadIdx.x;
    const int c0 = blockIdx.x * TCW;
    const int r0 = blockIdx.y * TRW;
    if (lt < KW) {
        float t = (float)(lt - RAD);
        hh[lt] = H_A * expf(-H_B * t * t);
    }

    // Stage: canvas rows r0+OFF .. +151, cols c0+OFF .. +87 (22 float4/row)
    for (int idx = lt; idx < INR * (INC / 4); idx += 256) {
        int row = idx / (INC / 4);
        int c4  = idx % (INC / 4);
        *reinterpret_cast<float4*>(&s[row * SSTR + c4 * 4]) =
            *reinterpret_cast<const float4*>(&g_pad[(r0 + OFF + row) * WP + c0 + OFF + c4 * 4]);
    }
    __syncthreads();

    // h-pass, two row-disjoint phases with in-place writeback.
    // Item mapping: row fastest (w % PH), group = w / PH.
#pragma unroll
    for (int ph = 0; ph < 2; ph++) {
        float acc[3][8];
#pragma unroll
        for (int it = 0; it < 3; it++) {
            int w = lt + it * 256;
#pragma unroll
            for (int j = 0; j < 8; j++) acc[it][j] = 0.f;
            if (w < PITEMS) {
                int row = ph * PH + (w % PH);
                int g   = w / PH;
                float x[32];
#pragma unroll
                for (int m = 0; m < 8; m++) {
                    float4 v = *reinterpret_cast<float4*>(&s[row * SSTR + g * 8 + m * 4]);
                    x[4 * m + 0] = v.x; x[4 * m + 1] = v.y;
                    x[4 * m + 2] = v.z; x[4 * m + 3] = v.w;
                }
#pragma unroll
                for (int u = 0; u < KW; u++) {
                    float hv = hh[u];
#pragma unroll
                    for (int j = 0; j < 8; j++)
                        acc[it][j] = fmaf(hv, x[u + j], acc[it][j]);
                }
            }
        }
        __syncthreads();
#pragma unroll
        for (int it = 0; it < 3; it++) {
            int w = lt + it * 256;
            if (w < PITEMS) {
                int row = ph * PH + (w % PH);
                int g   = w / PH;
                *reinterpret_cast<float4*>(&s[row * SSTR + g * 8]) =
                    make_float4(acc[it][0], acc[it][1], acc[it][2], acc[it][3]);
                *reinterpret_cast<float4*>(&s[row * SSTR + g * 8 + 4]) =
                    make_float4(acc[it][4], acc[it][5], acc[it][6], acc[it][7]);
            }
        }
        __syncthreads();
    }

    // v-pass: thread -> col c0+tx; two 16-row groups rg = ty, ty+4
    const int tx = lt & 63;
    const int ty = lt >> 6;
#pragma unroll
    for (int q = 0; q < 2; q++) {
        const int rg = ty + 4 * q;          // 0..7
        float x[16 + HAL];                  // 40
#pragma unroll
        for (int k = 0; k < 16 + HAL; k++) x[k] = s[(rg * 16 + k) * SSTR + tx];
        float a[16];
#pragma unroll
        for (int i = 0; i < 16; i++) a[i] = 0.f;
#pragma unroll
        for (int u = 0; u < KW; u++) {
            float hv = hh[u];
#pragma unroll
            for (int i = 0; i < 16; i++)
                a[i] = fmaf(hv, x[u + i], a[i]);
        }
#pragma unroll
        for (int i = 0; i < 16; i++)
            out[(r0 + rg * 16 + i) * OW + c0 + tx] = a[i];
    }
}

// ---------------------------------------------------------------------------
extern "C" void kernel_launch(void* const* d_in, const int* in_sizes, int n_in,
                              void* d_out, int out_size) {
    const float2* pos   = (const float2*)d_in[0];   // (N,2) float32 (x, y)
    const float*  inten = (const float*) d_in[1];   // (N,) float32
    const int n = in_sizes[1];
    float* out = (float*)d_out;

    cudaFuncSetAttribute(conv_kernel, cudaFuncAttributeMaxDynamicSharedMemorySize, SMEM_CONV);

    // Zero the canvas via a graph memset node (driver path saturates L2 writes)
    void* pad_ptr = nullptr;
    cudaGetSymbolAddress(&pad_ptr, g_pad);
    cudaMemsetAsync(pad_ptr, 0, (size_t)HP * WP * sizeof(float), 0);

    splat_kernel<<<(n + 255) / 256, 256>>>(pos, inten, n);
    conv_kernel<<<dim3(OW / TCW, OH / TRW), 256, SMEM_CONV>>>(out);
}

// round 17
// speedup vs baseline: 1.0567x; 1.0504x over previous
#include <cuda_runtime.h>
#include <math.h>

// Problem constants (fixed by reference_code)
#define HP   2080            // padded height = H + 2*margin
#define WP   2080            // padded width
#define OW   2048            // output width
#define OH   2048            // output height
#define MARG 16
#define RAD  12              // truncation radius (measured rel_err 1.6e-4 << 1e-3)
#define KW   (2*RAD + 1)     // 25 taps
#define OFF  (MARG - RAD)    // 4; no circular wrap needed (OFF >= 0)

// Closed-form real-space taps (exact by Poisson summation):
//   h[t] = SIG*sqrt(2*pi) * exp(-2*pi^2*SIG^2 * t^2)
#define H_A  0.12533141373155003f   // 0.05 * sqrt(2*pi)
#define H_B  0.04934802200544679f   // 2*pi^2*0.05^2

// Fused-conv tiling: output tile 64 cols x 128 rows
#define TCW  64              // tile cols (output)
#define TRW  128             // tile rows (output)
#define HAL  (2*RAD)         // 24
#define INR  (TRW + HAL)     // 152 staged rows
#define INC  (TCW + HAL)     // 88 staged cols
#define SSTR 92              // smem row stride (measured-best banking)
#define PH   (INR / 2)       // 76 rows per h-pass phase
#define PITEMS (PH * 8)      // 608 items per phase
#define SMEM_CONV (INR * SSTR * 4)   // 55936 B dynamic

// Scratch (device global: alloc-free per harness rules)
__device__ float g_pad[HP * WP];   // padded splat canvas

// ---------------------------------------------------------------------------
// 1) Zero canvas: 4 unrolled guarded STG.128 per thread, no grid-stride loop.
// ---------------------------------------------------------------------------
#define ZTH  270592                 // 1057 blocks x 256 threads
#define ZB   1057
__global__ void zero_kernel() {
    const int n4 = (HP * WP) / 4;   // 1,081,600
    float4* p = reinterpret_cast<float4*>(g_pad);
    const float4 z = make_float4(0.f, 0.f, 0.f, 0.f);
    int t = blockIdx.x * 256 + threadIdx.x;
#pragma unroll
    for (int k = 0; k < 4; k++) {
        int i = t + k * ZTH;
        if (i < n4) p[i] = z;
    }
}

// ---------------------------------------------------------------------------
// 2) Direct bilinear splat — transaction-minimal mix (R13-validated):
//    cx even      -> 2x red.v2 (2 trans)
//    cx % 4 == 1  -> 2x red.v4 (2 trans; cells at quad slots 1,2)
//    cx % 4 == 3  -> 4x scalar (4 trans; spans quads / wrap-safe)
//    avg 2.5 trans/point.
// ---------------------------------------------------------------------------
__device__ __forceinline__ void red4(float* p, float a, float b, float c, float d) {
    asm volatile("red.global.add.v4.f32 [%0], {%1, %2, %3, %4};"
                 :: "l"(p), "f"(a), "f"(b), "f"(c), "f"(d) : "memory");
}
__device__ __forceinline__ void red2(float* p, float a, float b) {
    asm volatile("red.global.add.v2.f32 [%0], {%1, %2};"
                 :: "l"(p), "f"(a), "f"(b) : "memory");
}

__global__ void splat_kernel(const float2* __restrict__ pos,
                             const float*  __restrict__ inten, int n) {
    int i = blockIdx.x * blockDim.x + threadIdx.x;
    if (i >= n) return;
    float2 p = pos[i];
    float px = p.x + (float)MARG;
    float py = p.y + (float)MARG;
    int cx = (int)floorf(px);
    int cy = (int)floorf(py);
    cx = min(max(cx, 0), WP - 1);
    cy = min(max(cy, 0), HP - 1);
    float dx = px - (float)cx;
    float dy = py - (float)cy;
    int cy1 = cy + 1; if (cy1 >= HP) cy1 = 0;
    float I = inten[i];
    float w00 = (1.f - dy) * (1.f - dx) * I;
    float w01 = (1.f - dy) * dx * I;
    float w10 = dy * (1.f - dx) * I;
    float w11 = dy * dx * I;
    int ra = cy  * WP;
    int rb = cy1 * WP;
    int m4 = cx & 3;
    if ((cx & 1) == 0) {                    // 8B-aligned pair (cx, cx+1); cx+1 <= 2079
        red2(&g_pad[ra + cx], w00, w01);
        red2(&g_pad[rb + cx], w10, w11);
    } else if (m4 == 1) {                   // cells at quad slots 1,2
        int b = cx & ~3;
        red4(&g_pad[ra + b], 0.f, w00, w01, 0.f);
        red4(&g_pad[rb + b], 0.f, w10, w11, 0.f);
    } else {                                // m4 == 3: spans quads (incl. wrap cx=2079)
        int cx1 = cx + 1; if (cx1 >= WP) cx1 = 0;
        atomicAdd(&g_pad[ra + cx ], w00);
        atomicAdd(&g_pad[rb + cx ], w10);
        atomicAdd(&g_pad[ra + cx1], w01);
        atomicAdd(&g_pad[rb + cx1], w11);
    }
}

// ---------------------------------------------------------------------------
// 3) Fused separable convolution + crop. One block = 64x128 output tile.
//    Taps inline (closed form). Stage 152x88 in dynamic smem (SSTR 92);
//    two-phase in-place h-pass; v-pass 2 x (40-float reg window, 16 outputs).
// ---------------------------------------------------------------------------
extern __shared__ float s[];
__global__ void __launch_bounds__(256, 4) conv_kernel(float* __restrict__ out) {
    __shared__ float hh[KW];
    const int lt = threadIdx.x;
    const int c0 = blockIdx.x * TCW;
    const int r0 = blockIdx.y * TRW;
    if (lt < KW) {
        float t = (float)(lt - RAD);
        hh[lt] = H_A * expf(-H_B * t * t);
    }

    // Stage: canvas rows r0+OFF .. +151, cols c0+OFF .. +87 (22 float4/row)
    for (int idx = lt; idx < INR * (INC / 4); idx += 256) {
        int row = idx / (INC / 4);
        int c4  = idx % (INC / 4);
        *reinterpret_cast<float4*>(&s[row * SSTR + c4 * 4]) =
            *reinterpret_cast<const float4*>(&g_pad[(r0 + OFF + row) * WP + c0 + OFF + c4 * 4]);
    }
    __syncthreads();

    // h-pass, two row-disjoint phases with in-place writeback.
    // Item mapping: row fastest (w % PH), group = w / PH.
#pragma unroll
    for (int ph = 0; ph < 2; ph++) {
        float acc[3][8];
#pragma unroll
        for (int it = 0; it < 3; it++) {
            int w = lt + it * 256;
#pragma unroll
            for (int j = 0; j < 8; j++) acc[it][j] = 0.f;
            if (w < PITEMS) {
                int row = ph * PH + (w % PH);
                int g   = w / PH;
                float x[32];
#pragma unroll
                for (int m = 0; m < 8; m++) {
                    float4 v = *reinterpret_cast<float4*>(&s[row * SSTR + g * 8 + m * 4]);
                    x[4 * m + 0] = v.x; x[4 * m + 1] = v.y;
                    x[4 * m + 2] = v.z; x[4 * m + 3] = v.w;
                }
#pragma unroll
                for (int u = 0; u < KW; u++) {
                    float hv = hh[u];
#pragma unroll
                    for (int j = 0; j < 8; j++)
                        acc[it][j] = fmaf(hv, x[u + j], acc[it][j]);
                }
            }
        }
        __syncthreads();
#pragma unroll
        for (int it = 0; it < 3; it++) {
            int w = lt + it * 256;
            if (w < PITEMS) {
                int row = ph * PH + (w % PH);
                int g   = w / PH;
                *reinterpret_cast<float4*>(&s[row * SSTR + g * 8]) =
                    make_float4(acc[it][0], acc[it][1], acc[it][2], acc[it][3]);
                *reinterpret_cast<float4*>(&s[row * SSTR + g * 8 + 4]) =
                    make_float4(acc[it][4], acc[it][5], acc[it][6], acc[it][7]);
            }
        }
        __syncthreads();
    }

    // v-pass: thread -> col c0+tx; two 16-row groups rg = ty, ty+4
    const int tx = lt & 63;
    const int ty = lt >> 6;
#pragma unroll
    for (int q = 0; q < 2; q++) {
        const int rg = ty + 4 * q;          // 0..7
        float x[16 + HAL];                  // 40
#pragma unroll
        for (int k = 0; k < 16 + HAL; k++) x[k] = s[(rg * 16 + k) * SSTR + tx];
        float a[16];
#pragma unroll
        for (int i = 0; i < 16; i++) a[i] = 0.f;
#pragma unroll
        for (int u = 0; u < KW; u++) {
            float hv = hh[u];
#pragma unroll
            for (int i = 0; i < 16; i++)
                a[i] = fmaf(hv, x[u + i], a[i]);
        }
#pragma unroll
        for (int i = 0; i < 16; i++)
            out[(r0 + rg * 16 + i) * OW + c0 + tx] = a[i];
    }
}

// ---------------------------------------------------------------------------
extern "C" void kernel_launch(void* const* d_in, const int* in_sizes, int n_in,
                              void* d_out, int out_size) {
    const float2* pos   = (const float2*)d_in[0];   // (N,2) float32 (x, y)
    const float*  inten = (const float*) d_in[1];   // (N,) float32
    const int n = in_sizes[1];
    float* out = (float*)d_out;

    cudaFuncSetAttribute(conv_kernel, cudaFuncAttributeMaxDynamicSharedMemorySize, SMEM_CONV);
    // Ask for the maximum shared-memory carveout: the 4th resident block needs
    // 4 x 55936 B = 223.7 KB of the 228 KB unified L1/shared.
    cudaFuncSetAttribute(conv_kernel, cudaFuncAttributePreferredSharedMemoryCarveout, 100);

    zero_kernel<<<ZB, 256>>>();
    splat_kernel<<<(n + 255) / 256, 256>>>(pos, inten, n);
    conv_kernel<<<dim3(OW / TCW, OH / TRW), 256, SMEM_CONV>>>(out);
}